// round 15
// baseline (speedup 1.0000x reference)
#include <cuda_runtime.h>
#include <cstdint>

#define BB 4
#define TT 1024
#define DD 768
#define LL 4
#define DFF 3072
#define VV 50257
#define NB 148
#define NT 512
#define NWARP (NB * (NT / 32))   // 2368 warps (k_main)
#define LSTRIDE 50260            // VV padded to multiple of 4
#define WIN 2048                 // broadcast column window (floats)
#define NWIN 25                  // ceil(VV / WIN)
#define RG 32                    // row groups (32 rows each)
#define XCH 96                   // split-K chunks held by x-partials (pw out)

// ---------------- scratch (static __device__, no allocations) ----------------
__device__ float g_kwm[DD];
__device__ float g_kbm;
__device__ float g_e[BB * TT];
__device__ float g_Z[BB];
__device__ __align__(16) float g_xpart[BB * 32 * DD];
__device__ float g_pA[96 * BB * DD];
__device__ float g_pB[96 * BB * DD];
__device__ __align__(16) float g_xn[BB * DD];
__device__ __align__(16) float g_logits[BB * LSTRIDE];

__device__ unsigned g_arrive;           // monotonic across launches
__device__ unsigned g_phase;

__device__ __forceinline__ float warp_sum(float v) {
    #pragma unroll
    for (int o = 16; o; o >>= 1) v += __shfl_xor_sync(0xffffffffu, v, o);
    return v;
}

// Lightweight grid barrier (148 co-resident blocks), monotonic across launches.
__device__ __forceinline__ void gsync(unsigned& gen) {
    __syncthreads();
    if (threadIdx.x == 0) {
        gen += NB;
        unsigned old;
        asm volatile("atom.acq_rel.gpu.add.u32 %0, [%1], 1;"
                     : "=r"(old) : "l"(&g_arrive) : "memory");
        if (old == gen - 1) {
            asm volatile("st.release.gpu.u32 [%0], %1;"
                         :: "l"(&g_phase), "r"(gen) : "memory");
        } else {
            unsigned cur;
            do {
                asm volatile("ld.acquire.gpu.u32 %0, [%1];"
                             : "=r"(cur) : "l"(&g_phase) : "memory");
            } while (cur < gen);
        }
    }
    __syncthreads();
}

// ---- skinny GEMM stage; W prefetched to registers BEFORE input reduction ----
// All MLP stages now run 144 blocks (NC * (K/KC)/2).
template<int KC>
__device__ __forceinline__ void gemm_stage(int srcXpart, const float* __restrict__ src,
                                           int srcKCH, const float* __restrict__ bias,
                                           int act, const float* __restrict__ W,
                                           int K, int N, int NC,
                                           float* __restrict__ dst, float* sA) {
    int blk = blockIdx.x, tid = threadIdx.x;
    int nblocks = NC * ((K / KC) / 2);
    if (blk < nblocks) {
        int nc = blk % NC;
        int kpair = blk / NC;
        int sub = tid >> 8;
        int n = nc * 256 + (tid & 255);
        int kch = kpair * 2 + sub;

        const float* Wp = W + (size_t)(kch * KC) * N + n;
        float wreg[KC];
        #pragma unroll
        for (int kk = 0; kk < KC; kk++) wreg[kk] = Wp[(size_t)kk * N];

        float rz[BB];
        if (srcXpart) {
            #pragma unroll
            for (int b = 0; b < BB; b++) rz[b] = 1.0f / __ldcg(&g_Z[b]);
        }

        for (int i = tid; i < 8 * KC; i += NT) {
            int s2 = i / (4 * KC);
            int rem = i - s2 * 4 * KC;
            int b = rem / KC, kk = rem - b * KC;
            int kg = (kpair * 2 + s2) * KC + kk;
            float v = 0.f;
            if (srcXpart) {
                #pragma unroll 8
                for (int c = 0; c < 32; c++)
                    v += __ldcg(&g_xpart[(size_t)(b * 32 + c) * DD + kg]);
                v *= rz[b];
            } else {
                #pragma unroll 8
                for (int kc = 0; kc < srcKCH; kc++)
                    v += __ldcg(&src[((size_t)kc * BB + b) * K + kg]);
            }
            if (bias) v += bias[kg];
            if (act) v = 0.5f * v * (1.0f + erff(v * 0.70710678118654752f));
            sA[(s2 * 4 + b) * KC + kk] = v;
        }
        __syncthreads();

        const float* a = sA + sub * 4 * KC;
        float a0 = 0.f, a1 = 0.f, a2 = 0.f, a3 = 0.f;
        #pragma unroll
        for (int kk = 0; kk < KC; kk++) {
            float w = wreg[kk];
            a0 += a[kk] * w;
            a1 += a[KC + kk] * w;
            a2 += a[2 * KC + kk] * w;
            a3 += a[3 * KC + kk] * w;
        }
        size_t base = (size_t)kch * BB * N + n;
        __stcg(&dst[base],         a0);
        __stcg(&dst[base + N],     a1);
        __stcg(&dst[base + 2 * N], a2);
        __stcg(&dst[base + 3 * N], a3);
        __syncthreads();
    }
}

// ============ persistent kernel: embeddings ... ln_f ... logits ==============
__global__ __launch_bounds__(NT, 1)
void k_main(const int* __restrict__ idx, const float* __restrict__ wte,
            const float* __restrict__ wpe, const float* __restrict__ lnw,
            const float* __restrict__ kw,  const float* __restrict__ kb,
            const float* __restrict__ vw,  const float* __restrict__ vb,
            const float* __restrict__ fcw, const float* __restrict__ pw) {
    __shared__ __align__(16) float sm[BB * DD];
    __shared__ int smi[32];
    int blk = blockIdx.x, tid = threadIdx.x;
    int lane = tid & 31, wid = tid >> 5;
    int gw = blk * (NT / 32) + wid;

    unsigned gen;
    asm volatile("ld.acquire.gpu.u32 %0, [%1];" : "=r"(gen) : "l"(&g_phase) : "memory");

    // S0: kwm[i] = mean_d kw0[i,d]; kbm = mean(kb0)  (float4 row sums)
    for (int i = gw; i < DD; i += NWARP) {
        const float4* row = (const float4*)(kw + (size_t)i * DD);
        float s = 0.f;
        #pragma unroll
        for (int jj = 0; jj < DD / 128; jj++) {
            float4 r = row[lane + jj * 32];
            s += r.x + r.y + r.z + r.w;
        }
        s = warp_sum(s);
        if (lane == 0) __stcg(&g_kwm[i], s * (1.0f / DD));
    }
    if (gw == NWARP - 1) {
        const float4* kb4 = (const float4*)kb;
        float s = 0.f;
        #pragma unroll
        for (int jj = 0; jj < DD / 128; jj++) {
            float4 r = kb4[lane + jj * 32];
            s += r.x + r.y + r.z + r.w;
        }
        s = warp_sum(s);
        if (lane == 0) __stcg(&g_kbm, s * (1.0f / DD));
    }
    gsync(gen);

    // S1: e[b,t] = exp(cos((wte[idx]+wpe[t]).kwm + kbm))  (float4 dot)
    for (int i = tid; i < DD; i += NT) sm[i] = __ldcg(&g_kwm[i]);
    __syncthreads();
    {
        float4* sm4 = (float4*)sm;
        float kbm = __ldcg(&g_kbm);
        for (int tok = gw; tok < BB * TT; tok += NWARP) {
            int t = tok & (TT - 1);
            const float4* e4 = (const float4*)(wte + (size_t)idx[tok] * DD);
            const float4* p4 = (const float4*)(wpe + (size_t)t * DD);
            float s = 0.f;
            #pragma unroll
            for (int jj = 0; jj < DD / 128; jj++) {
                int j = lane + jj * 32;
                float4 e = e4[j], p = p4[j], k = sm4[j];
                s += (e.x + p.x) * k.x + (e.y + p.y) * k.y
                   + (e.z + p.z) * k.z + (e.w + p.w) * k.w;
            }
            s = warp_sum(s);
            if (lane == 0) __stcg(&g_e[tok], expf(cosf(s + kbm)));
        }
    }
    gsync(gen);

    // S2 (merged): blocks 0-3 compute Z[b]; blocks 4-131 xbar partials (float4)
    if (blk < BB) {
        float v0 = __ldcg(&g_e[blk * TT + tid]);
        float v1 = __ldcg(&g_e[blk * TT + tid + 512]);
        sm[tid] = v0 + v1; __syncthreads();
        for (int o = 256; o; o >>= 1) { if (tid < o) sm[tid] += sm[tid + o]; __syncthreads(); }
        if (tid == 0) __stcg(&g_Z[blk], sm[0]);
    } else if (blk < 132) {
        int b = (blk - 4) >> 5, c = (blk - 4) & 31;
        if (tid < 32) {
            int t = c * 32 + tid;
            sm[tid]  = __ldcg(&g_e[b * TT + t]);
            smi[tid] = idx[b * TT + t];
        }
        __syncthreads();
        if (tid < DD / 4) {
            float4 acc = make_float4(0.f, 0.f, 0.f, 0.f);
            #pragma unroll 8
            for (int j = 0; j < 32; j++) {
                int t = c * 32 + j;
                float w = sm[j];
                float4 e = ((const float4*)(wte + (size_t)smi[j] * DD))[tid];
                float4 p = ((const float4*)(wpe + (size_t)t * DD))[tid];
                acc.x += w * (e.x + p.x);
                acc.y += w * (e.y + p.y);
                acc.z += w * (e.z + p.z);
                acc.w += w * (e.w + p.w);
            }
            __stcg(&((float4*)(g_xpart + (size_t)((b * 32 + c)) * DD))[tid], acc);
        }
    }
    gsync(gen);

    // 4 layers; KC: vw 8, fcw 32, pw 32 -> all stages use 144 blocks.
    // Output chunk counts: vw 96, fcw 24, pw 96.
    float* P[2] = {g_pA, g_pB};
    int xb = -1;
    for (int l = 0; l < LL; l++) {
        const float* vwl  = vw  + (size_t)l * DD * DD;
        const float* vbl  = vb  + (size_t)l * DD;
        const float* fcwl = fcw + (size_t)l * DD * DFF;
        const float* pwl  = pw  + (size_t)l * DFF * DD;

        float* d0 = (xb == 1) ? P[0] : ((xb == 0) ? P[1] : P[0]);
        float* d1 = (d0 == P[0]) ? P[1] : P[0];
        const float* xsrc = (xb < 0) ? nullptr : P[xb];

        gemm_stage<8>(xb < 0, xsrc, XCH, nullptr, 0, vwl, DD, DD, 3, d0, sm);    // 144 blk
        gsync(gen);
        gemm_stage<32>(0, d0, 96, vbl, 0, fcwl, DD, DFF, 12, d1, sm);            // 144 blk
        gsync(gen);
        gemm_stage<32>(0, d1, 24, nullptr, 1, pwl, DFF, DD, 3, d0, sm);          // 144 blk
        gsync(gen);
        xb = (d0 == P[0]) ? 0 : 1;
    }

    // ln_f (blocks 0..3), reducing final partials (XCH=96 chunks) -> g_xn
    if (blk < BB) {
        const float* Px = P[xb];
        float v0 = 0.f, v1 = 0.f;
        #pragma unroll 8
        for (int kc = 0; kc < XCH; kc++)
            v0 += __ldcg(&Px[((size_t)kc * BB + blk) * DD + tid]);
        if (tid < 256) {
            #pragma unroll 8
            for (int kc = 0; kc < XCH; kc++)
                v1 += __ldcg(&Px[((size_t)kc * BB + blk) * DD + tid + 512]);
        }
        sm[tid] = v0 + v1; __syncthreads();
        for (int o = 256; o; o >>= 1) { if (tid < o) sm[tid] += sm[tid + o]; __syncthreads(); }
        float mu = sm[0] * (1.0f / DD); __syncthreads();
        float d0 = v0 - mu, d1 = (tid < 256) ? (v1 - mu) : 0.f;
        sm[tid] = d0 * d0 + ((tid < 256) ? d1 * d1 : 0.f); __syncthreads();
        for (int o = 256; o; o >>= 1) { if (tid < o) sm[tid] += sm[tid + o]; __syncthreads(); }
        float rstd = rsqrtf(sm[0] * (1.0f / DD) + 1e-5f);
        __stcg(&g_xn[blk * DD + tid], d0 * rstd * lnw[tid]);
        if (tid < 256) __stcg(&g_xn[blk * DD + tid + 512], d1 * rstd * lnw[tid + 512]);
    }
    gsync(gen);

    // logits: 2 vocab rows per warp, streaming loads (__ldcs) for wte
    {
        float4* sxn4 = (float4*)sm;
        for (int i = tid; i < BB * DD / 4; i += NT)
            sxn4[i] = __ldcg(&((const float4*)g_xn)[i]);
        __syncthreads();
        for (int v = gw * 2; v < VV; v += NWARP * 2) {
            bool two = (v + 1) < VV;
            const float4* wr0 = (const float4*)(wte + (size_t)v * DD);
            const float4* wr1 = (const float4*)(wte + (size_t)(v + 1) * DD);
            float a0 = 0.f, a1 = 0.f, a2 = 0.f, a3 = 0.f;
            float b0 = 0.f, b1 = 0.f, b2 = 0.f, b3 = 0.f;
            #pragma unroll
            for (int jj = 0; jj < DD / 128; jj++) {
                int j = lane + jj * 32;
                float4 w0 = __ldcs(&wr0[j]);
                float4 w1 = two ? __ldcs(&wr1[j]) : make_float4(0.f, 0.f, 0.f, 0.f);
                float4 x0 = sxn4[j];
                float4 x1 = sxn4[192 + j];
                float4 x2 = sxn4[384 + j];
                float4 x3 = sxn4[576 + j];
                a0 += w0.x * x0.x + w0.y * x0.y + w0.z * x0.z + w0.w * x0.w;
                a1 += w0.x * x1.x + w0.y * x1.y + w0.z * x1.z + w0.w * x1.w;
                a2 += w0.x * x2.x + w0.y * x2.y + w0.z * x2.z + w0.w * x2.w;
                a3 += w0.x * x3.x + w0.y * x3.y + w0.z * x3.z + w0.w * x3.w;
                b0 += w1.x * x0.x + w1.y * x0.y + w1.z * x0.z + w1.w * x0.w;
                b1 += w1.x * x1.x + w1.y * x1.y + w1.z * x1.z + w1.w * x1.w;
                b2 += w1.x * x2.x + w1.y * x2.y + w1.z * x2.z + w1.w * x2.w;
                b3 += w1.x * x3.x + w1.y * x3.y + w1.z * x3.z + w1.w * x3.w;
            }
            a0 = warp_sum(a0); a1 = warp_sum(a1); a2 = warp_sum(a2); a3 = warp_sum(a3);
            b0 = warp_sum(b0); b1 = warp_sum(b1); b2 = warp_sum(b2); b3 = warp_sum(b3);
            if (lane == 0) {
                __stcg(&g_logits[v],               a0);
                __stcg(&g_logits[LSTRIDE + v],     a1);
                __stcg(&g_logits[2 * LSTRIDE + v], a2);
                __stcg(&g_logits[3 * LSTRIDE + v], a3);
                if (two) {
                    __stcg(&g_logits[v + 1],               b0);
                    __stcg(&g_logits[LSTRIDE + v + 1],     b1);
                    __stcg(&g_logits[2 * LSTRIDE + v + 1], b2);
                    __stcg(&g_logits[3 * LSTRIDE + v + 1], b3);
                }
            }
        }
    }
}

// =============== broadcast: unchanged (at the 5.44 TB/s write roofline) ======
__global__ __launch_bounds__(256)
void k_bcast(float* __restrict__ out) {
    __shared__ __align__(16) float smf[WIN + 4];
    float4* sm4 = (float4*)smf;
    int tid = threadIdx.x, warp = tid >> 5, lane = tid & 31;

    int blk = blockIdx.x;
    int b   = blk & 3;
    int rest = blk >> 2;
    int win = rest % NWIN;
    int rg  = rest / NWIN;

    int w0 = win * WIN;
    int wlen = VV - w0; if (wlen > WIN) wlen = WIN;

    const float* src = g_logits + (size_t)b * LSTRIDE + w0;
    for (int i = tid; i < wlen; i += 256) smf[i] = __ldcg(&src[i]);
    __syncthreads();

    #pragma unroll
    for (int rr = 0; rr < 4; rr++) {
        int r = rg * 32 + rr * 8 + warp;
        int a = r & 3;
        int head = (4 - a) & 3;
        int nvec = (wlen - head) >> 2;
        int tail = wlen - head - 4 * nvec;

        float* dst = out + (size_t)(b * TT + r) * VV + w0;
        if (lane < head) dst[lane] = smf[lane];
        float4* d4 = (float4*)(dst + head);
        if (a == 0) {
            for (int i = lane; i < nvec; i += 32) __stcs(d4 + i, sm4[i]);
        } else if (a == 3) {
            for (int i = lane; i < nvec; i += 32) {
                float4 x = sm4[i], y = sm4[i + 1];
                __stcs(d4 + i, make_float4(x.y, x.z, x.w, y.x));
            }
        } else if (a == 2) {
            for (int i = lane; i < nvec; i += 32) {
                float4 x = sm4[i], y = sm4[i + 1];
                __stcs(d4 + i, make_float4(x.z, x.w, y.x, y.y));
            }
        } else {
            for (int i = lane; i < nvec; i += 32) {
                float4 x = sm4[i], y = sm4[i + 1];
                __stcs(d4 + i, make_float4(x.w, y.x, y.y, y.z));
            }
        }
        if (lane < tail) dst[head + 4 * nvec + lane] = smf[head + 4 * nvec + lane];
    }
}

// ---------------- launch ------------------------------------------------------
extern "C" void kernel_launch(void* const* d_in, const int* in_sizes, int n_in,
                              void* d_out, int out_size) {
    const int*   idx = (const int*)  d_in[0];
    const float* wte = (const float*)d_in[1];
    const float* wpe = (const float*)d_in[2];
    const float* lnw = (const float*)d_in[3];
    // d_in[4]=qw, d_in[5]=qb : dead (scores independent of Q)
    const float* kw  = (const float*)d_in[6];
    const float* kb  = (const float*)d_in[7];
    const float* vw  = (const float*)d_in[8];
    const float* vb  = (const float*)d_in[9];
    const float* fcw = (const float*)d_in[10];
    const float* pw  = (const float*)d_in[11];
    float* out = (float*)d_out;

    k_main<<<NB, NT>>>(idx, wte, wpe, lnw, kw, kb, vw, vb, fcw, pw);
    k_bcast<<<BB * NWIN * RG, 256>>>(out);
}

// round 16
// speedup vs baseline: 1.0119x; 1.0119x over previous
#include <cuda_runtime.h>
#include <cstdint>

#define BB 4
#define TT 1024
#define DD 768
#define LL 4
#define DFF 3072
#define VV 50257
#define NB 148
#define NT 512
#define NWARP (NB * (NT / 32))   // 2368 warps (k_main)
#define LSTRIDE 50260            // VV padded to multiple of 4
#define WIN 2048                 // broadcast column window (floats)
#define NWIN 25                  // ceil(VV / WIN)
#define RG 32                    // row groups (32 rows each)
#define XCH 48                   // split-K chunks held by x-partials

// ---------------- scratch (static __device__, no allocations) ----------------
__device__ float g_kwm[DD];
__device__ float g_kbm;
__device__ float g_e[BB * TT];
__device__ float g_Z[BB];
__device__ float g_xpart[BB * 32 * DD];
__device__ float g_pA[96 * BB * DD];
__device__ float g_pB[96 * BB * DD];
__device__ __align__(16) float g_xn[BB * DD];
__device__ __align__(16) float g_logits[BB * LSTRIDE];

__device__ unsigned g_arrive;           // monotonic across launches
__device__ unsigned g_phase;

__device__ __forceinline__ float warp_sum(float v) {
    #pragma unroll
    for (int o = 16; o; o >>= 1) v += __shfl_xor_sync(0xffffffffu, v, o);
    return v;
}

// Lightweight grid barrier (148 co-resident blocks), monotonic across launches.
__device__ __forceinline__ void gsync(unsigned& gen) {
    __syncthreads();
    if (threadIdx.x == 0) {
        gen += NB;
        unsigned old;
        asm volatile("atom.acq_rel.gpu.add.u32 %0, [%1], 1;"
                     : "=r"(old) : "l"(&g_arrive) : "memory");
        if (old == gen - 1) {
            asm volatile("st.release.gpu.u32 [%0], %1;"
                         :: "l"(&g_phase), "r"(gen) : "memory");
        } else {
            unsigned cur;
            do {
                asm volatile("ld.acquire.gpu.u32 %0, [%1];"
                             : "=r"(cur) : "l"(&g_phase) : "memory");
            } while (cur < gen);
        }
    }
    __syncthreads();
}

// ---- skinny GEMM stage; W prefetched to registers BEFORE input reduction ----
template<int KC>
__device__ __forceinline__ void gemm_stage(int srcXpart, const float* __restrict__ src,
                                           int srcKCH, const float* __restrict__ bias,
                                           int act, const float* __restrict__ W,
                                           int K, int N, int NC,
                                           float* __restrict__ dst, float* sA) {
    int blk = blockIdx.x, tid = threadIdx.x;
    int nblocks = NC * ((K / KC) / 2);
    if (blk < nblocks) {
        int nc = blk % NC;
        int kpair = blk / NC;
        int sub = tid >> 8;
        int n = nc * 256 + (tid & 255);
        int kch = kpair * 2 + sub;

        const float* Wp = W + (size_t)(kch * KC) * N + n;
        float wreg[KC];
        #pragma unroll
        for (int kk = 0; kk < KC; kk++) wreg[kk] = Wp[(size_t)kk * N];

        float rz[BB];
        if (srcXpart) {
            #pragma unroll
            for (int b = 0; b < BB; b++) rz[b] = 1.0f / __ldcg(&g_Z[b]);
        }

        for (int i = tid; i < 8 * KC; i += NT) {
            int s2 = i / (4 * KC);
            int rem = i - s2 * 4 * KC;
            int b = rem / KC, kk = rem - b * KC;
            int kg = (kpair * 2 + s2) * KC + kk;
            float v = 0.f;
            if (srcXpart) {
                #pragma unroll 8
                for (int c = 0; c < 32; c++)
                    v += __ldcg(&g_xpart[(size_t)(b * 32 + c) * DD + kg]);
                v *= rz[b];
            } else {
                #pragma unroll 8
                for (int kc = 0; kc < srcKCH; kc++)
                    v += __ldcg(&src[((size_t)kc * BB + b) * K + kg]);
            }
            if (bias) v += bias[kg];
            if (act) v = 0.5f * v * (1.0f + erff(v * 0.70710678118654752f));
            sA[(s2 * 4 + b) * KC + kk] = v;
        }
        __syncthreads();

        const float* a = sA + sub * 4 * KC;
        float a0 = 0.f, a1 = 0.f, a2 = 0.f, a3 = 0.f;
        #pragma unroll
        for (int kk = 0; kk < KC; kk++) {
            float w = wreg[kk];
            a0 += a[kk] * w;
            a1 += a[KC + kk] * w;
            a2 += a[2 * KC + kk] * w;
            a3 += a[3 * KC + kk] * w;
        }
        size_t base = (size_t)kch * BB * N + n;
        __stcg(&dst[base],         a0);
        __stcg(&dst[base + N],     a1);
        __stcg(&dst[base + 2 * N], a2);
        __stcg(&dst[base + 3 * N], a3);
    }
}

// ============ persistent kernel: embeddings ... ln_f ... logits ==============
__global__ __launch_bounds__(NT, 1)
void k_main(const int* __restrict__ idx, const float* __restrict__ wte,
            const float* __restrict__ wpe, const float* __restrict__ lnw,
            const float* __restrict__ kw,  const float* __restrict__ kb,
            const float* __restrict__ vw,  const float* __restrict__ vb,
            const float* __restrict__ fcw, const float* __restrict__ pw) {
    __shared__ __align__(16) float sm[BB * DD];
    __shared__ int smi[32];
    int blk = blockIdx.x, tid = threadIdx.x;
    int lane = tid & 31, wid = tid >> 5;
    int gw = blk * (NT / 32) + wid;

    unsigned gen;
    asm volatile("ld.acquire.gpu.u32 %0, [%1];" : "=r"(gen) : "l"(&g_phase) : "memory");

    // S0: kwm[i] = mean_d kw0[i,d]; kbm = mean(kb0)
    for (int i = gw; i < DD; i += NWARP) {
        const float* row = kw + (size_t)i * DD;
        float s = 0.f;
        #pragma unroll
        for (int jj = 0; jj < DD / 32; jj++) s += row[lane + jj * 32];
        s = warp_sum(s);
        if (lane == 0) __stcg(&g_kwm[i], s * (1.0f / DD));
    }
    if (gw == NWARP - 1) {
        float s = 0.f;
        #pragma unroll
        for (int jj = 0; jj < DD / 32; jj++) s += kb[lane + jj * 32];
        s = warp_sum(s);
        if (lane == 0) __stcg(&g_kbm, s * (1.0f / DD));
    }
    gsync(gen);

    // S1: e[b,t] = exp(cos((wte[idx]+wpe[t]).kwm + kbm))
    for (int i = tid; i < DD; i += NT) sm[i] = __ldcg(&g_kwm[i]);
    __syncthreads();
    {
        float kbm = __ldcg(&g_kbm);
        for (int tok = gw; tok < BB * TT; tok += NWARP) {
            int t = tok & (TT - 1);
            const float* e = wte + (size_t)idx[tok] * DD;
            const float* p = wpe + (size_t)t * DD;
            float s = 0.f;
            #pragma unroll
            for (int jj = 0; jj < DD / 32; jj++) {
                int j = lane + jj * 32;
                s += (e[j] + p[j]) * sm[j];
            }
            s = warp_sum(s);
            if (lane == 0) __stcg(&g_e[tok], expf(cosf(s + kbm)));
        }
    }
    gsync(gen);

    // S2 (merged): blocks 0-3 compute Z[b]; blocks 4-131 compute xbar partials
    if (blk < BB) {
        float v0 = __ldcg(&g_e[blk * TT + tid]);
        float v1 = __ldcg(&g_e[blk * TT + tid + 512]);
        sm[tid] = v0 + v1; __syncthreads();
        for (int o = 256; o; o >>= 1) { if (tid < o) sm[tid] += sm[tid + o]; __syncthreads(); }
        if (tid == 0) __stcg(&g_Z[blk], sm[0]);
    } else if (blk < 132) {
        int b = (blk - 4) >> 5, c = (blk - 4) & 31;
        if (tid < 32) {
            int t = c * 32 + tid;
            sm[tid]  = __ldcg(&g_e[b * TT + t]);
            smi[tid] = idx[b * TT + t];
        }
        __syncthreads();
        for (int d = tid; d < DD; d += NT) {
            float acc = 0.f;
            #pragma unroll 8
            for (int j = 0; j < 32; j++) {
                int t = c * 32 + j;
                acc += sm[j] * (wte[(size_t)smi[j] * DD + d] + wpe[(size_t)t * DD + d]);
            }
            __stcg(&g_xpart[(size_t)((b * 32 + c)) * DD + d], acc);
        }
    }
    gsync(gen);

    // 4 layers, split-K partials ping-pong; reductions fused into consumers.
    float* P[2] = {g_pA, g_pB};
    int xb = -1;
    for (int l = 0; l < LL; l++) {
        const float* vwl  = vw  + (size_t)l * DD * DD;
        const float* vbl  = vb  + (size_t)l * DD;
        const float* fcwl = fcw + (size_t)l * DD * DFF;
        const float* pwl  = pw  + (size_t)l * DFF * DD;

        float* d0 = (xb == 1) ? P[0] : ((xb == 0) ? P[1] : P[0]);
        float* d1 = (d0 == P[0]) ? P[1] : P[0];
        const float* xsrc = (xb < 0) ? nullptr : P[xb];

        gemm_stage<16>(xb < 0, xsrc, XCH, nullptr, 0, vwl, DD, DD, 3, d0, sm);
        gsync(gen);
        gemm_stage<32>(0, d0, 48, vbl, 0, fcwl, DD, DFF, 12, d1, sm);
        gsync(gen);
        gemm_stage<64>(0, d1, 24, nullptr, 1, pwl, DFF, DD, 3, d0, sm);
        gsync(gen);
        xb = (d0 == P[0]) ? 0 : 1;
    }

    // ln_f (blocks 0..3), reducing final partials -> g_xn
    if (blk < BB) {
        const float* Px = P[xb];
        float v0 = 0.f, v1 = 0.f;
        #pragma unroll 8
        for (int kc = 0; kc < XCH; kc++)
            v0 += __ldcg(&Px[((size_t)kc * BB + blk) * DD + tid]);
        if (tid < 256) {
            #pragma unroll 8
            for (int kc = 0; kc < XCH; kc++)
                v1 += __ldcg(&Px[((size_t)kc * BB + blk) * DD + tid + 512]);
        }
        sm[tid] = v0 + v1; __syncthreads();
        for (int o = 256; o; o >>= 1) { if (tid < o) sm[tid] += sm[tid + o]; __syncthreads(); }
        float mu = sm[0] * (1.0f / DD); __syncthreads();
        float d0 = v0 - mu, d1 = (tid < 256) ? (v1 - mu) : 0.f;
        sm[tid] = d0 * d0 + ((tid < 256) ? d1 * d1 : 0.f); __syncthreads();
        for (int o = 256; o; o >>= 1) { if (tid < o) sm[tid] += sm[tid + o]; __syncthreads(); }
        float rstd = rsqrtf(sm[0] * (1.0f / DD) + 1e-5f);
        __stcg(&g_xn[blk * DD + tid], d0 * rstd * lnw[tid]);
        if (tid < 256) __stcg(&g_xn[blk * DD + tid + 512], d1 * rstd * lnw[tid + 512]);
    }
    gsync(gen);

    // logits: 4 vocab rows per warp (deep MLP), streaming loads for wte
    {
        float4* sxn4 = (float4*)sm;
        for (int i = tid; i < BB * DD / 4; i += NT)
            sxn4[i] = __ldcg(&((const float4*)g_xn)[i]);
        __syncthreads();
        for (int v = gw * 4; v < VV; v += NWARP * 4) {
            bool t1 = (v + 1) < VV, t2 = (v + 2) < VV, t3 = (v + 3) < VV;
            const float4* wr0 = (const float4*)(wte + (size_t)v * DD);
            const float4* wr1 = (const float4*)(wte + (size_t)(v + 1) * DD);
            const float4* wr2 = (const float4*)(wte + (size_t)(v + 2) * DD);
            const float4* wr3 = (const float4*)(wte + (size_t)(v + 3) * DD);
            float acc[4][4] = {};
            #pragma unroll
            for (int jj = 0; jj < DD / 128; jj++) {
                int j = lane + jj * 32;
                float4 w0 = __ldcs(&wr0[j]);
                float4 w1 = t1 ? __ldcs(&wr1[j]) : make_float4(0.f, 0.f, 0.f, 0.f);
                float4 w2 = t2 ? __ldcs(&wr2[j]) : make_float4(0.f, 0.f, 0.f, 0.f);
                float4 w3 = t3 ? __ldcs(&wr3[j]) : make_float4(0.f, 0.f, 0.f, 0.f);
                #pragma unroll
                for (int b = 0; b < BB; b++) {
                    float4 x = sxn4[b * 192 + j];
                    acc[0][b] += w0.x * x.x + w0.y * x.y + w0.z * x.z + w0.w * x.w;
                    acc[1][b] += w1.x * x.x + w1.y * x.y + w1.z * x.z + w1.w * x.w;
                    acc[2][b] += w2.x * x.x + w2.y * x.y + w2.z * x.z + w2.w * x.w;
                    acc[3][b] += w3.x * x.x + w3.y * x.y + w3.z * x.z + w3.w * x.w;
                }
            }
            #pragma unroll
            for (int r = 0; r < 4; r++)
                #pragma unroll
                for (int b = 0; b < BB; b++)
                    acc[r][b] = warp_sum(acc[r][b]);
            if (lane == 0) {
                #pragma unroll
                for (int r = 0; r < 4; r++) {
                    if (v + r < VV) {
                        #pragma unroll
                        for (int b = 0; b < BB; b++)
                            __stcg(&g_logits[(size_t)b * LSTRIDE + v + r], acc[r][b]);
                    }
                }
            }
        }
    }
}

// =============== broadcast: unchanged (at the 5.44 TB/s write roofline) ======
__global__ __launch_bounds__(256)
void k_bcast(float* __restrict__ out) {
    __shared__ __align__(16) float smf[WIN + 4];
    float4* sm4 = (float4*)smf;
    int tid = threadIdx.x, warp = tid >> 5, lane = tid & 31;

    int blk = blockIdx.x;
    int b   = blk & 3;
    int rest = blk >> 2;
    int win = rest % NWIN;
    int rg  = rest / NWIN;

    int w0 = win * WIN;
    int wlen = VV - w0; if (wlen > WIN) wlen = WIN;

    const float* src = g_logits + (size_t)b * LSTRIDE + w0;
    for (int i = tid; i < wlen; i += 256) smf[i] = __ldcg(&src[i]);
    __syncthreads();

    #pragma unroll
    for (int rr = 0; rr < 4; rr++) {
        int r = rg * 32 + rr * 8 + warp;
        int a = r & 3;
        int head = (4 - a) & 3;
        int nvec = (wlen - head) >> 2;
        int tail = wlen - head - 4 * nvec;

        float* dst = out + (size_t)(b * TT + r) * VV + w0;
        if (lane < head) dst[lane] = smf[lane];
        float4* d4 = (float4*)(dst + head);
        if (a == 0) {
            for (int i = lane; i < nvec; i += 32) __stcs(d4 + i, sm4[i]);
        } else if (a == 3) {
            for (int i = lane; i < nvec; i += 32) {
                float4 x = sm4[i], y = sm4[i + 1];
                __stcs(d4 + i, make_float4(x.y, x.z, x.w, y.x));
            }
        } else if (a == 2) {
            for (int i = lane; i < nvec; i += 32) {
                float4 x = sm4[i], y = sm4[i + 1];
                __stcs(d4 + i, make_float4(x.z, x.w, y.x, y.y));
            }
        } else {
            for (int i = lane; i < nvec; i += 32) {
                float4 x = sm4[i], y = sm4[i + 1];
                __stcs(d4 + i, make_float4(x.w, y.x, y.y, y.z));
            }
        }
        if (lane < tail) dst[head + 4 * nvec + lane] = smf[head + 4 * nvec + lane];
    }
}

// ---------------- launch ------------------------------------------------------
extern "C" void kernel_launch(void* const* d_in, const int* in_sizes, int n_in,
                              void* d_out, int out_size) {
    const int*   idx = (const int*)  d_in[0];
    const float* wte = (const float*)d_in[1];
    const float* wpe = (const float*)d_in[2];
    const float* lnw = (const float*)d_in[3];
    // d_in[4]=qw, d_in[5]=qb : dead (scores independent of Q)
    const float* kw  = (const float*)d_in[6];
    const float* kb  = (const float*)d_in[7];
    const float* vw  = (const float*)d_in[8];
    const float* vb  = (const float*)d_in[9];
    const float* fcw = (const float*)d_in[10];
    const float* pw  = (const float*)d_in[11];
    float* out = (float*)d_out;

    k_main<<<NB, NT>>>(idx, wte, wpe, lnw, kw, kb, vw, vb, fcw, pw);
    k_bcast<<<BB * NWIN * RG, 256>>>(out);
}

// round 17
// speedup vs baseline: 1.0748x; 1.0622x over previous
#include <cuda_runtime.h>
#include <cstdint>

#define BB 4
#define TT 1024
#define DD 768
#define LL 4
#define DFF 3072
#define VV 50257
#define NB 148
#define NT 512
#define NWARP (NB * (NT / 32))   // 2368 warps (k_main)
#define LSTRIDE 50260            // VV padded to multiple of 4
#define WIN 2048                 // broadcast column window (floats)
#define NWIN 25                  // ceil(VV / WIN)
#define RG 32                    // row groups (32 rows each)

// ---------------- scratch (static __device__, no allocations) ----------------
__device__ float g_kwm[DD];
__device__ float g_kbm;
__device__ float g_e[BB * TT];
__device__ float g_Z[BB];
__device__ float g_x[BB * DD];          // RED accumulator: xbar, then layer x
__device__ float g_ctx[BB * DD];        // RED accumulator: x@vw
__device__ float g_h[BB * DFF];         // RED accumulator: ctx@fcw
__device__ __align__(16) float g_xn[BB * DD];
__device__ __align__(16) float g_logits[BB * LSTRIDE];

__device__ unsigned g_arrive;           // monotonic across launches
__device__ unsigned g_phase;

__device__ __forceinline__ float warp_sum(float v) {
    #pragma unroll
    for (int o = 16; o; o >>= 1) v += __shfl_xor_sync(0xffffffffu, v, o);
    return v;
}

// Lightweight grid barrier (148 co-resident blocks), monotonic across launches.
// release/acquire chain also orders prior RED (atomicAdd) traffic.
__device__ __forceinline__ void gsync(unsigned& gen) {
    __syncthreads();
    if (threadIdx.x == 0) {
        gen += NB;
        unsigned old;
        asm volatile("atom.acq_rel.gpu.add.u32 %0, [%1], 1;"
                     : "=r"(old) : "l"(&g_arrive) : "memory");
        if (old == gen - 1) {
            asm volatile("st.release.gpu.u32 [%0], %1;"
                         :: "l"(&g_phase), "r"(gen) : "memory");
        } else {
            unsigned cur;
            do {
                asm volatile("ld.acquire.gpu.u32 %0, [%1];"
                             : "=r"(cur) : "l"(&g_phase) : "memory");
            } while (cur < gen);
        }
    }
    __syncthreads();
}

// zero a buffer cooperatively (all 148 blocks)
__device__ __forceinline__ void zero_buf(float* p, int n) {
    for (int i = blockIdx.x * NT + threadIdx.x; i < n; i += NB * NT)
        __stcg(&p[i], 0.f);
}

// ---- skinny GEMM stage with RED accumulation -------------------------------
// Input src is a FINALIZED (B,K) vector (1 load per element); optional rz
// (softmax 1/Z), bias, exact GELU applied on the input side. Output k-chunk
// contributions are atomicAdd'ed into dst (pre-zeroed one stage earlier).
template<int KC>
__device__ __forceinline__ void gemm_acc(int useRz, const float* __restrict__ src,
                                         const float* __restrict__ bias, int act,
                                         const float* __restrict__ W,
                                         int K, int N, int NC,
                                         float* __restrict__ dst, float* sA) {
    int blk = blockIdx.x, tid = threadIdx.x;
    int nblocks = NC * ((K / KC) / 2);
    if (blk < nblocks) {
        int nc = blk % NC;
        int kpair = blk / NC;
        int sub = tid >> 8;
        int n = nc * 256 + (tid & 255);
        int kch = kpair * 2 + sub;

        const float* Wp = W + (size_t)(kch * KC) * N + n;
        float wreg[KC];
        #pragma unroll
        for (int kk = 0; kk < KC; kk++) wreg[kk] = Wp[(size_t)kk * N];

        float rz[BB];
        if (useRz) {
            #pragma unroll
            for (int b = 0; b < BB; b++) rz[b] = 1.0f / __ldcg(&g_Z[b]);
        }

        for (int i = tid; i < 8 * KC; i += NT) {
            int s2 = i / (4 * KC);
            int rem = i - s2 * 4 * KC;
            int b = rem / KC, kk = rem - b * KC;
            int kg = (kpair * 2 + s2) * KC + kk;
            float v = __ldcg(&src[b * K + kg]);
            if (useRz) v *= rz[b];
            if (bias) v += bias[kg];
            if (act) v = 0.5f * v * (1.0f + erff(v * 0.70710678118654752f));
            sA[(s2 * 4 + b) * KC + kk] = v;
        }
        __syncthreads();

        const float* a = sA + sub * 4 * KC;
        float a0 = 0.f, a1 = 0.f, a2 = 0.f, a3 = 0.f;
        #pragma unroll
        for (int kk = 0; kk < KC; kk++) {
            float w = wreg[kk];
            a0 += a[kk] * w;
            a1 += a[KC + kk] * w;
            a2 += a[2 * KC + kk] * w;
            a3 += a[3 * KC + kk] * w;
        }
        atomicAdd(&dst[n],         a0);
        atomicAdd(&dst[N + n],     a1);
        atomicAdd(&dst[2 * N + n], a2);
        atomicAdd(&dst[3 * N + n], a3);
        __syncthreads();
    }
}

// ============ persistent kernel: embeddings ... ln_f ... logits ==============
__global__ __launch_bounds__(NT, 1)
void k_main(const int* __restrict__ idx, const float* __restrict__ wte,
            const float* __restrict__ wpe, const float* __restrict__ lnw,
            const float* __restrict__ kw,  const float* __restrict__ kb,
            const float* __restrict__ vw,  const float* __restrict__ vb,
            const float* __restrict__ fcw, const float* __restrict__ pw) {
    __shared__ __align__(16) float sm[BB * DD];
    __shared__ int smi[32];
    int blk = blockIdx.x, tid = threadIdx.x;
    int lane = tid & 31, wid = tid >> 5;
    int gw = blk * (NT / 32) + wid;

    unsigned gen;
    asm volatile("ld.acquire.gpu.u32 %0, [%1];" : "=r"(gen) : "l"(&g_phase) : "memory");

    // S0: kwm, kbm; zero g_x and g_ctx (accumulated later)
    zero_buf(g_x, BB * DD);
    zero_buf(g_ctx, BB * DD);
    for (int i = gw; i < DD; i += NWARP) {
        const float* row = kw + (size_t)i * DD;
        float s = 0.f;
        #pragma unroll
        for (int jj = 0; jj < DD / 32; jj++) s += row[lane + jj * 32];
        s = warp_sum(s);
        if (lane == 0) __stcg(&g_kwm[i], s * (1.0f / DD));
    }
    if (gw == NWARP - 1) {
        float s = 0.f;
        #pragma unroll
        for (int jj = 0; jj < DD / 32; jj++) s += kb[lane + jj * 32];
        s = warp_sum(s);
        if (lane == 0) __stcg(&g_kbm, s * (1.0f / DD));
    }
    gsync(gen);

    // S1: e[b,t] = exp(cos((wte[idx]+wpe[t]).kwm + kbm))
    for (int i = tid; i < DD; i += NT) sm[i] = __ldcg(&g_kwm[i]);
    __syncthreads();
    {
        float kbm = __ldcg(&g_kbm);
        for (int tok = gw; tok < BB * TT; tok += NWARP) {
            int t = tok & (TT - 1);
            const float* e = wte + (size_t)idx[tok] * DD;
            const float* p = wpe + (size_t)t * DD;
            float s = 0.f;
            #pragma unroll
            for (int jj = 0; jj < DD / 32; jj++) {
                int j = lane + jj * 32;
                s += (e[j] + p[j]) * sm[j];
            }
            s = warp_sum(s);
            if (lane == 0) __stcg(&g_e[tok], expf(cosf(s + kbm)));
        }
    }
    gsync(gen);

    // S2: blocks 0-3 compute Z[b]; blocks 4-131 RED xbar chunks into g_x
    if (blk < BB) {
        float v0 = __ldcg(&g_e[blk * TT + tid]);
        float v1 = __ldcg(&g_e[blk * TT + tid + 512]);
        sm[tid] = v0 + v1; __syncthreads();
        for (int o = 256; o; o >>= 1) { if (tid < o) sm[tid] += sm[tid + o]; __syncthreads(); }
        if (tid == 0) __stcg(&g_Z[blk], sm[0]);
    } else if (blk < 132) {
        int b = (blk - 4) >> 5, c = (blk - 4) & 31;
        if (tid < 32) {
            int t = c * 32 + tid;
            sm[tid]  = __ldcg(&g_e[b * TT + t]);
            smi[tid] = idx[b * TT + t];
        }
        __syncthreads();
        for (int d = tid; d < DD; d += NT) {
            float acc = 0.f;
            #pragma unroll 8
            for (int j = 0; j < 32; j++) {
                int t = c * 32 + j;
                acc += sm[j] * (wte[(size_t)smi[j] * DD + d] + wpe[(size_t)t * DD + d]);
            }
            atomicAdd(&g_x[b * DD + d], acc);
        }
    }
    gsync(gen);

    // 4 layers; finalized buffers + RED accumulation; zero one stage ahead.
    for (int l = 0; l < LL; l++) {
        const float* vwl  = vw  + (size_t)l * DD * DD;
        const float* vbl  = vb  + (size_t)l * DD;
        const float* fcwl = fcw + (size_t)l * DD * DFF;
        const float* pwl  = pw  + (size_t)l * DFF * DD;

        // vw: ctx += x@vw   (x /Z on layer 0); zero h for fcw
        gemm_acc<16>(l == 0, g_x, nullptr, 0, vwl, DD, DD, 3, g_ctx, sm);
        zero_buf(g_h, BB * DFF);
        gsync(gen);
        // fcw: h += (ctx+vb)@fcw; zero x for pw
        gemm_acc<32>(0, g_ctx, vbl, 0, fcwl, DD, DFF, 12, g_h, sm);
        zero_buf(g_x, BB * DD);
        gsync(gen);
        // pw: x += gelu(h)@pw; zero ctx for next layer
        gemm_acc<64>(0, g_h, nullptr, 1, pwl, DFF, DD, 3, g_x, sm);
        zero_buf(g_ctx, BB * DD);
        gsync(gen);
    }

    // ln_f (blocks 0..3) on finalized g_x -> g_xn
    if (blk < BB) {
        float v0 = __ldcg(&g_x[blk * DD + tid]);
        float v1 = (tid < 256) ? __ldcg(&g_x[blk * DD + tid + 512]) : 0.f;
        sm[tid] = v0 + v1; __syncthreads();
        for (int o = 256; o; o >>= 1) { if (tid < o) sm[tid] += sm[tid + o]; __syncthreads(); }
        float mu = sm[0] * (1.0f / DD); __syncthreads();
        float d0 = v0 - mu, d1 = (tid < 256) ? (v1 - mu) : 0.f;
        sm[tid] = d0 * d0 + ((tid < 256) ? d1 * d1 : 0.f); __syncthreads();
        for (int o = 256; o; o >>= 1) { if (tid < o) sm[tid] += sm[tid + o]; __syncthreads(); }
        float rstd = rsqrtf(sm[0] * (1.0f / DD) + 1e-5f);
        __stcg(&g_xn[blk * DD + tid], d0 * rstd * lnw[tid]);
        if (tid < 256) __stcg(&g_xn[blk * DD + tid + 512], d1 * rstd * lnw[tid + 512]);
    }
    gsync(gen);

    // logits: 2 vocab rows per warp, streaming loads (__ldcs) for wte
    {
        float4* sxn4 = (float4*)sm;
        for (int i = tid; i < BB * DD / 4; i += NT)
            sxn4[i] = __ldcg(&((const float4*)g_xn)[i]);
        __syncthreads();
        for (int v = gw * 2; v < VV; v += NWARP * 2) {
            bool two = (v + 1) < VV;
            const float4* wr0 = (const float4*)(wte + (size_t)v * DD);
            const float4* wr1 = (const float4*)(wte + (size_t)(v + 1) * DD);
            float a0 = 0.f, a1 = 0.f, a2 = 0.f, a3 = 0.f;
            float b0 = 0.f, b1 = 0.f, b2 = 0.f, b3 = 0.f;
            #pragma unroll
            for (int jj = 0; jj < DD / 128; jj++) {
                int j = lane + jj * 32;
                float4 w0 = __ldcs(&wr0[j]);
                float4 w1 = two ? __ldcs(&wr1[j]) : make_float4(0.f, 0.f, 0.f, 0.f);
                float4 x0 = sxn4[j];
                float4 x1 = sxn4[192 + j];
                float4 x2 = sxn4[384 + j];
                float4 x3 = sxn4[576 + j];
                a0 += w0.x * x0.x + w0.y * x0.y + w0.z * x0.z + w0.w * x0.w;
                a1 += w0.x * x1.x + w0.y * x1.y + w0.z * x1.z + w0.w * x1.w;
                a2 += w0.x * x2.x + w0.y * x2.y + w0.z * x2.z + w0.w * x2.w;
                a3 += w0.x * x3.x + w0.y * x3.y + w0.z * x3.z + w0.w * x3.w;
                b0 += w1.x * x0.x + w1.y * x0.y + w1.z * x0.z + w1.w * x0.w;
                b1 += w1.x * x1.x + w1.y * x1.y + w1.z * x1.z + w1.w * x1.w;
                b2 += w1.x * x2.x + w1.y * x2.y + w1.z * x2.z + w1.w * x2.w;
                b3 += w1.x * x3.x + w1.y * x3.y + w1.z * x3.z + w1.w * x3.w;
            }
            a0 = warp_sum(a0); a1 = warp_sum(a1); a2 = warp_sum(a2); a3 = warp_sum(a3);
            b0 = warp_sum(b0); b1 = warp_sum(b1); b2 = warp_sum(b2); b3 = warp_sum(b3);
            if (lane == 0) {
                __stcg(&g_logits[v],               a0);
                __stcg(&g_logits[LSTRIDE + v],     a1);
                __stcg(&g_logits[2 * LSTRIDE + v], a2);
                __stcg(&g_logits[3 * LSTRIDE + v], a3);
                if (two) {
                    __stcg(&g_logits[v + 1],               b0);
                    __stcg(&g_logits[LSTRIDE + v + 1],     b1);
                    __stcg(&g_logits[2 * LSTRIDE + v + 1], b2);
                    __stcg(&g_logits[3 * LSTRIDE + v + 1], b3);
                }
            }
        }
    }
}

// =============== broadcast: unchanged (at the 5.44 TB/s write roofline) ======
__global__ __launch_bounds__(256)
void k_bcast(float* __restrict__ out) {
    __shared__ __align__(16) float smf[WIN + 4];
    float4* sm4 = (float4*)smf;
    int tid = threadIdx.x, warp = tid >> 5, lane = tid & 31;

    int blk = blockIdx.x;
    int b   = blk & 3;
    int rest = blk >> 2;
    int win = rest % NWIN;
    int rg  = rest / NWIN;

    int w0 = win * WIN;
    int wlen = VV - w0; if (wlen > WIN) wlen = WIN;

    const float* src = g_logits + (size_t)b * LSTRIDE + w0;
    for (int i = tid; i < wlen; i += 256) smf[i] = __ldcg(&src[i]);
    __syncthreads();

    #pragma unroll
    for (int rr = 0; rr < 4; rr++) {
        int r = rg * 32 + rr * 8 + warp;
        int a = r & 3;
        int head = (4 - a) & 3;
        int nvec = (wlen - head) >> 2;
        int tail = wlen - head - 4 * nvec;

        float* dst = out + (size_t)(b * TT + r) * VV + w0;
        if (lane < head) dst[lane] = smf[lane];
        float4* d4 = (float4*)(dst + head);
        if (a == 0) {
            for (int i = lane; i < nvec; i += 32) __stcs(d4 + i, sm4[i]);
        } else if (a == 3) {
            for (int i = lane; i < nvec; i += 32) {
                float4 x = sm4[i], y = sm4[i + 1];
                __stcs(d4 + i, make_float4(x.y, x.z, x.w, y.x));
            }
        } else if (a == 2) {
            for (int i = lane; i < nvec; i += 32) {
                float4 x = sm4[i], y = sm4[i + 1];
                __stcs(d4 + i, make_float4(x.z, x.w, y.x, y.y));
            }
        } else {
            for (int i = lane; i < nvec; i += 32) {
                float4 x = sm4[i], y = sm4[i + 1];
                __stcs(d4 + i, make_float4(x.w, y.x, y.y, y.z));
            }
        }
        if (lane < tail) dst[head + 4 * nvec + lane] = smf[head + 4 * nvec + lane];
    }
}

// ---------------- launch ------------------------------------------------------
extern "C" void kernel_launch(void* const* d_in, const int* in_sizes, int n_in,
                              void* d_out, int out_size) {
    const int*   idx = (const int*)  d_in[0];
    const float* wte = (const float*)d_in[1];
    const float* wpe = (const float*)d_in[2];
    const float* lnw = (const float*)d_in[3];
    // d_in[4]=qw, d_in[5]=qb : dead (scores independent of Q)
    const float* kw  = (const float*)d_in[6];
    const float* kb  = (const float*)d_in[7];
    const float* vw  = (const float*)d_in[8];
    const float* vb  = (const float*)d_in[9];
    const float* fcw = (const float*)d_in[10];
    const float* pw  = (const float*)d_in[11];
    float* out = (float*)d_out;

    k_main<<<NB, NT>>>(idx, wte, wpe, lnw, kw, kb, vw, vb, fcw, pw);
    k_bcast<<<BB * NWIN * RG, 256>>>(out);
}